// round 7
// baseline (speedup 1.0000x reference)
#include <cuda_runtime.h>
#include <stdint.h>

// ---------------- constants ----------------
#define MAXN_LAB  (1 << 18)          // label scratch capacity (N = 200000 fits)
#define MAXC_FAST 108                // fast path: C*256*4 <= ~110KB (2 blocks/SM)
#define ENC_NINF  ((int)0x807FFFFF)  // order-preserving encoding of -inf
#define F_NINF    __int_as_float(0xff800000)

// ---------------- device scratch (static: no allocation) ----------------
__device__ int g_off[MAXN_LAB + 16];   // pre-scaled smem byte offsets: label*1024
__device__ int g_is64;
__device__ unsigned int g_done;        // last-block counter (reset every launch)

// Order-preserving float<->int bijection (self-inverse, monotone for non-NaN).
__device__ __forceinline__ int enc_f(float f) {
    int i = __float_as_int(f);
    return (i >= 0) ? i : (i ^ 0x7fffffff);
}

// ---------------- kernel 0: init output + flags + width detect ------------
// int64 labels in [0,C) have every odd int32 word == 0 (little endian).
__global__ void smp_init_detect(int* __restrict__ out_enc, int BC,
                                const int* __restrict__ l32, int N) {
    int i = blockIdx.x * blockDim.x + threadIdx.x;
    if (i == 0) { g_is64 = 1; g_done = 0; }
    if (i < BC) out_enc[i] = ENC_NINF;
    if (i < N && (i & 1) && l32[i] != 0) g_is64 = 0;  // racy same-value store: fine
}

// ---------------- kernel 1: compact labels -> pre-scaled byte offsets -----
// offset = c * 1024  (acc stride per class = 256 threads * 4B)
__global__ void smp_compact(const void* __restrict__ labels, int N) {
    int i = blockIdx.x * blockDim.x + threadIdx.x;
    if (i < N) {
        int v = g_is64 ? (int)((const long long*)labels)[i]
                       : ((const int*)labels)[i];
        g_off[i] = v << 10;
    }
}

// ---------------- RMW of one lane-quad against private smem cells ---------
// Batched stale reads (one LDS window per 4 elements) + branchless duplicate
// forward-propagation make the batched reads exact: the last store to any
// duplicated address carries the running max. Same-thread may-alias smem
// ordering handles collisions across successive calls.
__device__ __forceinline__ void rmw_quad(char* aB, float4 v, int4 o) {
    float* a0 = (float*)(aB + o.x);
    float* a1 = (float*)(aB + o.y);
    float* a2 = (float*)(aB + o.z);
    float* a3 = (float*)(aB + o.w);
    float s0 = *a0, s1 = *a1, s2 = *a2, s3 = *a3;
    if (o.x == o.y) v.y = fmaxf(v.y, v.x);
    if (o.x == o.z) v.z = fmaxf(v.z, v.x);
    if (o.y == o.z) v.z = fmaxf(v.z, v.y);
    if (o.x == o.w) v.w = fmaxf(v.w, v.x);
    if (o.y == o.w) v.w = fmaxf(v.w, v.y);
    if (o.z == o.w) v.w = fmaxf(v.w, v.z);
    *a0 = fmaxf(s0, v.x);
    *a1 = fmaxf(s1, v.y);
    *a2 = fmaxf(s2, v.z);
    *a3 = fmaxf(s3, v.w);
}

// ---------------- kernel 2: main streaming max + fused final decode -------
// Grid (slices, ceil(B/8)), 256 threads (8 warps; warp w owns one row).
// Lane-private accumulators acc[c*256 + tid]: conflict-free banks, single
// owner, no atomics in the hot loop. Unroll x2: 4 batched LDG.128 per
// iteration (MLP=4, ~2KB in flight per warp) feeding two sequential smem
// RMW phases. Merge via warp shfl-max + one global atomicMax per (warp,c).
// The last block to finish decodes out_enc in place (threadfence+counter).
__global__ __launch_bounds__(256, 2) void smp_main(
    const float* __restrict__ vals, int* __restrict__ out_enc,
    int B, int N, int C, int JW, int nblocks, int BC)
{
    extern __shared__ float acc[];          // [C][256]
    __shared__ int is_last_s;
    const int tid  = threadIdx.x;
    const int w    = tid >> 5;
    const int lane = tid & 31;
    const int row  = blockIdx.y * 8 + w;
    const int j0   = blockIdx.x * JW;

    // Init private cells. Disjoint ownership: no sync needed.
    #pragma unroll 4
    for (int c = 0; c < C; c++) acc[c * 256 + tid] = F_NINF;

    if (row < B && j0 < N) {
        const int n  = min(JW, N - j0);
        const int n4 = n >> 2;
        const float4* rp = (const float4*)(vals + (size_t)row * N + j0);
        const int4*   op = (const int4*)(g_off + j0);
        char* aB = (char*)acc + (tid << 2);

        int  i   = lane;
        bool any = (i < n4);
        bool two = (i + 32 < n4);
        float4 v0, v1; int4 o0, o1;
        if (any) { v0 = __ldcs(rp + i);      o0 = op[i]; }
        if (two) { v1 = __ldcs(rp + i + 32); o1 = op[i + 32]; }

        while (any) {
            const int  j   = i + 64;
            const bool m1  = (j < n4);
            const bool m2  = (j + 32 < n4);
            const int  jp  = m1 ? j      : i;   // clamped, in-bounds prefetch
            const int  jp2 = m2 ? j + 32 : i;
            float4 w0 = __ldcs(rp + jp);  int4 p0 = op[jp];
            float4 w1 = __ldcs(rp + jp2); int4 p1 = op[jp2];

            rmw_quad(aB, v0, o0);                 // phase A
            if (two) rmw_quad(aB, v1, o1);        // phase B (ordered after A)

            v0 = w0; o0 = p0; v1 = w1; o1 = p1;
            any = m1; two = m2; i = j;
        }
        // Scalar tail (n % 4 != 0).
        const int tail = n & 3;
        if (lane < tail) {
            int col = j0 + (n4 << 2) + lane;
            float x = vals[(size_t)row * N + col];
            float* a = (float*)(aB + g_off[col]);
            *a = fmaxf(*a, x);
        }
    }
    // No __syncthreads needed before merge: each thread reads only its cells.

    if (row < B) {
        int* orow = out_enc + row * C;
        for (int c = 0; c < C; c++) {
            float m = acc[c * 256 + tid];
            #pragma unroll
            for (int off = 16; off; off >>= 1)
                m = fmaxf(m, __shfl_xor_sync(0xffffffffu, m, off));
            if (lane == 0 && m > F_NINF)
                atomicMax(orow + c, enc_f(m));
        }
    }

    // ---- fused finalize: last block decodes encoded ints in place ----
    __threadfence();                         // my atomics -> visible device-wide
    __syncthreads();                         // all threads of block fenced
    if (tid == 0)
        is_last_s = (atomicAdd(&g_done, 1u) == (unsigned)(nblocks - 1));
    __syncthreads();
    if (is_last_s) {
        volatile int* vo = (volatile int*)out_enc;
        for (int k = tid; k < BC; k += 256) {
            int e = vo[k];
            out_enc[k] = (e >= 0) ? e : (e ^ 0x7fffffff);
        }
    }
}

// ---------------- fallback: fully general (C > MAXC_FAST or N > MAXN_LAB) --
__global__ void smp_naive(const float* __restrict__ vals, const void* __restrict__ labels,
                          int* __restrict__ out_enc, int B, int N, int C)
{
    long long total  = (long long)B * N;
    long long stride = (long long)gridDim.x * blockDim.x;
    int is64 = g_is64;
    for (long long idx = blockIdx.x * (long long)blockDim.x + threadIdx.x;
         idx < total; idx += stride) {
        int j = (int)(idx % N);
        int b = (int)(idx / N);
        int c = is64 ? (int)((const long long*)labels)[j]
                     : ((const int*)labels)[j];
        atomicMax(out_enc + b * C + c, enc_f(vals[idx]));
    }
}

// ---------------- decode kernel (naive path only) ----------------
__global__ void smp_fin(int* __restrict__ io, int BC) {
    int i = blockIdx.x * blockDim.x + threadIdx.x;
    if (i < BC) {
        int e = io[i];
        io[i] = (e >= 0) ? e : (e ^ 0x7fffffff);
    }
}

// ---------------- launch ----------------
extern "C" void kernel_launch(void* const* d_in, const int* in_sizes, int n_in,
                              void* d_out, int out_size)
{
    const float* vals   = (const float*)d_in[0];
    const void*  labels = d_in[1];

    const int NV = in_sizes[0];      // B * N
    const int N  = in_sizes[1];      // 200000
    const int B  = NV / N;           // 128
    const int BC = out_size;         // B * C
    const int C  = BC / B;           // 100
    int* out_enc = (int*)d_out;

    const bool fast = (C <= MAXC_FAST) && (N <= MAXN_LAB) &&
                      ((size_t)B * N == (size_t)NV);

    int tmax = (N > BC) ? N : BC;
    smp_init_detect<<<(tmax + 255) / 256, 256>>>(out_enc, BC, (const int*)labels, N);

    if (fast) {
        smp_compact<<<(N + 255) / 256, 256>>>(labels, N);

        // Single wave: <= 296 resident blocks (2 per SM at ~100KB smem each).
        const size_t smem = (size_t)C * 256 * sizeof(float);
        static int smem_set = 0;
        if (!smem_set) {
            cudaFuncSetAttribute(smp_main,
                cudaFuncAttributeMaxDynamicSharedMemorySize, 113 * 1024);
            smem_set = 1;
        }
        int rowBlocks = (B + 7) / 8;              // 16
        int S = 296 / rowBlocks;                  // 18 column slices
        if (S < 1) S = 1;
        int JW = ((N + S - 1) / S + 3) & ~3;      // quad-aligned slice width
        dim3 grid((N + JW - 1) / JW, rowBlocks);
        int nblocks = grid.x * grid.y;
        smp_main<<<grid, 256, smem>>>(vals, out_enc, B, N, C, JW, nblocks, BC);
    } else {
        smp_naive<<<1184, 256>>>(vals, labels, out_enc, B, N, C);
        smp_fin<<<(BC + 255) / 256, 256>>>(out_enc, BC);
    }
}

// round 8
// speedup vs baseline: 1.0261x; 1.0261x over previous
#include <cuda_runtime.h>
#include <stdint.h>

// ---------------- constants ----------------
#define MAXN_LAB  (1 << 18)          // label scratch capacity (N = 200000 fits)
#define MAXC_FAST 108                // fast path: C*256*4 <= ~110KB (2 blocks/SM)
#define ENC_NINF  ((int)0x807FFFFF)  // order-preserving encoding of -inf
#define F_NINF    __int_as_float(0xff800000)

// ---------------- device scratch (static: no allocation) ----------------
__device__ int g_off[MAXN_LAB + 16];   // pre-scaled smem byte offsets: label*1024
__device__ int g_is64;
__device__ unsigned int g_done;        // last-block counter (reset every launch)

// Order-preserving float<->int bijection (self-inverse, monotone for non-NaN).
__device__ __forceinline__ int enc_f(float f) {
    int i = __float_as_int(f);
    return (i >= 0) ? i : (i ^ 0x7fffffff);
}

// ---------------- kernel 0: init output + flags + sampled width detect ----
// int64 labels in [0,C) have every odd int32 word == 0 (little endian).
// Block 0 samples ~10k odd words: if labels were int32, those words are
// labels themselves and are nonzero w.h.p. for any nondegenerate data.
__global__ void smp_init(int* __restrict__ out_enc, int BC,
                         const int* __restrict__ l32, int N) {
    int i = blockIdx.x * blockDim.x + threadIdx.x;
    if (i == 0) { g_is64 = 1; g_done = 0; }
    if (i < BC) out_enc[i] = ENC_NINF;
    if (blockIdx.x == 0) {
        int lim = (N < 20000) ? N : 20000;
        int found32 = 0;
        for (int k = threadIdx.x; k < lim; k += 256)
            if ((k & 1) && l32[k] != 0) found32 = 1;
        if (__syncthreads_or(found32)) {
            if (threadIdx.x == 0) g_is64 = 0;
        }
    }
}

// ---------------- kernel 1: compact labels -> pre-scaled byte offsets -----
// offset = c * 1024  (acc stride per class = 256 threads * 4B)
__global__ void smp_compact(const void* __restrict__ labels, int N) {
    int i = blockIdx.x * blockDim.x + threadIdx.x;
    if (i < N) {
        int v = g_is64 ? (int)((const long long*)labels)[i]
                       : ((const int*)labels)[i];
        g_off[i] = v << 10;
    }
}

// ---------------- kernel 2: main streaming max + fused final decode -------
// Grid (slices, ceil(B/8)), 256 threads (8 warps; warp w owns one row).
// Lane-private accumulators acc[c*256 + tid]:
//   - bank = lane for every access -> conflict-free for ANY label pattern
//   - single owner -> no races, no atomics, no branches in the hot loop
// Hot loop per lane-quad (PROVEN round-5 form):
//   - batched LDS x4 of stale cells (one latency window per 4 elements)
//   - branchless duplicate forward-propagation makes batched stale reads
//     exact (last store to a duplicated address carries the running max)
//   - register double-buffer prefetch of the next quad (values via __ldcs)
// Merge: warp shfl-max per class + one global atomicMax per (warp, class).
// Finalize: last block to finish decodes out_enc in place (ldcg, pipelined).
__global__ __launch_bounds__(256, 2) void smp_main(
    const float* __restrict__ vals, int* __restrict__ out_enc,
    int B, int N, int C, int JW, int nblocks, int BC)
{
    extern __shared__ float acc[];          // [C][256]
    __shared__ int is_last_s;
    const int tid  = threadIdx.x;
    const int w    = tid >> 5;
    const int lane = tid & 31;
    const int row  = blockIdx.y * 8 + w;
    const int j0   = blockIdx.x * JW;

    // Init private cells. Disjoint ownership: no sync needed.
    #pragma unroll 4
    for (int c = 0; c < C; c++) acc[c * 256 + tid] = F_NINF;

    if (row < B && j0 < N) {
        const int n  = min(JW, N - j0);
        const int n4 = n >> 2;
        const float4* rp = (const float4*)(vals + (size_t)row * N + j0);
        const int4*   op = (const int4*)(g_off + j0);
        char* aB = (char*)acc + (tid << 2);

        int i = lane;
        float4 v; int4 o;
        bool any = (i < n4);
        if (any) { v = __ldcs(rp + i); o = op[i]; }
        while (any) {
            const int inext = i + 32;
            const bool more = (inext < n4);
            const int  ip   = more ? inext : i;        // clamped, in-bounds
            float4 vn = __ldcs(rp + ip);               // prefetch next quad
            int4   on = op[ip];

            float* a0 = (float*)(aB + o.x);
            float* a1 = (float*)(aB + o.y);
            float* a2 = (float*)(aB + o.z);
            float* a3 = (float*)(aB + o.w);
            // Batched stale reads: one LDS latency window per 4 elements.
            float s0 = *a0, s1 = *a1, s2 = *a2, s3 = *a3;
            // Duplicate-safe forward propagation (fills the LDS wait).
            if (o.x == o.y) v.y = fmaxf(v.y, v.x);
            if (o.x == o.z) v.z = fmaxf(v.z, v.x);
            if (o.y == o.z) v.z = fmaxf(v.z, v.y);
            if (o.x == o.w) v.w = fmaxf(v.w, v.x);
            if (o.y == o.w) v.w = fmaxf(v.w, v.y);
            if (o.z == o.w) v.w = fmaxf(v.w, v.z);
            // Stores in order: last store to a duplicated address wins and
            // carries the propagated max -> exact.
            *a0 = fmaxf(s0, v.x);
            *a1 = fmaxf(s1, v.y);
            *a2 = fmaxf(s2, v.z);
            *a3 = fmaxf(s3, v.w);

            v = vn; o = on; i = inext; any = more;
        }
        // Scalar tail (n % 4 != 0).
        const int tail = n & 3;
        if (lane < tail) {
            int col = j0 + (n4 << 2) + lane;
            float x = vals[(size_t)row * N + col];
            float* a = (float*)(aB + g_off[col]);
            *a = fmaxf(*a, x);
        }
    }
    // No __syncthreads needed before merge: each thread reads only its cells.

    if (row < B) {
        int* orow = out_enc + row * C;
        for (int c = 0; c < C; c++) {
            float m = acc[c * 256 + tid];
            #pragma unroll
            for (int off = 16; off; off >>= 1)
                m = fmaxf(m, __shfl_xor_sync(0xffffffffu, m, off));
            if (lane == 0 && m > F_NINF)
                atomicMax(orow + c, enc_f(m));
        }
    }

    // ---- fused finalize: last finishing block decodes in place ----
    __threadfence();                         // my atomics -> visible device-wide
    __syncthreads();                         // whole block past its fence
    if (tid == 0)
        is_last_s = (atomicAdd(&g_done, 1u) == (unsigned)(nblocks - 1));
    __syncthreads();
    if (is_last_s) {
        // All other blocks fenced before bumping the counter, and atomics
        // live in L2: __ldcg reads see the final encoded values. Loads are
        // independent -> fully pipelined (no volatile ordering chain).
        for (int k = tid; k < BC; k += 256) {
            int e = __ldcg(out_enc + k);
            out_enc[k] = (e >= 0) ? e : (e ^ 0x7fffffff);
        }
    }
}

// ---------------- fallback: fully general (C > MAXC_FAST or N > MAXN_LAB) --
__global__ void smp_naive(const float* __restrict__ vals, const void* __restrict__ labels,
                          int* __restrict__ out_enc, int B, int N, int C)
{
    long long total  = (long long)B * N;
    long long stride = (long long)gridDim.x * blockDim.x;
    int is64 = g_is64;
    for (long long idx = blockIdx.x * (long long)blockDim.x + threadIdx.x;
         idx < total; idx += stride) {
        int j = (int)(idx % N);
        int b = (int)(idx / N);
        int c = is64 ? (int)((const long long*)labels)[j]
                     : ((const int*)labels)[j];
        atomicMax(out_enc + b * C + c, enc_f(vals[idx]));
    }
}

// ---------------- decode kernel (naive path only) ----------------
__global__ void smp_fin(int* __restrict__ io, int BC) {
    int i = blockIdx.x * blockDim.x + threadIdx.x;
    if (i < BC) {
        int e = io[i];
        io[i] = (e >= 0) ? e : (e ^ 0x7fffffff);
    }
}

// ---------------- launch ----------------
extern "C" void kernel_launch(void* const* d_in, const int* in_sizes, int n_in,
                              void* d_out, int out_size)
{
    const float* vals   = (const float*)d_in[0];
    const void*  labels = d_in[1];

    const int NV = in_sizes[0];      // B * N
    const int N  = in_sizes[1];      // 200000
    const int B  = NV / N;           // 128
    const int BC = out_size;         // B * C
    const int C  = BC / B;           // 100
    int* out_enc = (int*)d_out;

    const bool fast = (C <= MAXC_FAST) && (N <= MAXN_LAB) &&
                      ((size_t)B * N == (size_t)NV);

    smp_init<<<(BC + 255) / 256, 256>>>(out_enc, BC, (const int*)labels, N);

    if (fast) {
        smp_compact<<<(N + 255) / 256, 256>>>(labels, N);

        // Single wave: <= 296 resident blocks (2 per SM at ~100KB smem each).
        const size_t smem = (size_t)C * 256 * sizeof(float);
        static int smem_set = 0;
        if (!smem_set) {
            cudaFuncSetAttribute(smp_main,
                cudaFuncAttributeMaxDynamicSharedMemorySize, 113 * 1024);
            smem_set = 1;
        }
        int rowBlocks = (B + 7) / 8;              // 16
        int S = 296 / rowBlocks;                  // 18 column slices
        if (S < 1) S = 1;
        int JW = ((N + S - 1) / S + 3) & ~3;      // quad-aligned slice width
        dim3 grid((N + JW - 1) / JW, rowBlocks);
        int nblocks = grid.x * grid.y;
        smp_main<<<grid, 256, smem>>>(vals, out_enc, B, N, C, JW, nblocks, BC);
    } else {
        smp_naive<<<1184, 256>>>(vals, labels, out_enc, B, N, C);
        smp_fin<<<(BC + 255) / 256, 256>>>(out_enc, BC);
    }
}